// round 1
// baseline (speedup 1.0000x reference)
#include <cuda_runtime.h>

#define RAD 5
#define WIN 11
#define TX 32
#define TY 8
#define PPT 2
#define TILE_H (TY * PPT)            // 16
#define HALO_W (TX + 2 * RAD)        // 42
#define HALO_H (TILE_H + 2 * RAD)    // 26
#define NPIX   (HALO_W * HALO_H)     // 1092
#define IMG_H 1024
#define IMG_W 1024

__global__ __launch_bounds__(TX * TY)
void bilateral_kernel(const float* __restrict__ col,
                      const float* __restrict__ nrm,
                      const float* __restrict__ zdz,
                      float* __restrict__ out)
{
    __shared__ float4 s_colz[NPIX];        // col.rgb, z
    __shared__ float4 s_nrm[NPIX];         // nrm.xyz, pad
    __shared__ float2 s_lut[WIN * WIN];    // (1/dist, dist^2/8)

    const int tx = threadIdx.x;
    const int ty = threadIdx.y;
    const int tid = ty * TX + tx;
    const int b  = blockIdx.z;
    const int x0 = blockIdx.x * TX;
    const int y0 = blockIdx.y * TILE_H;

    // ---- fill LUT (121 entries) ----
    if (tid < WIN * WIN) {
        int dy = tid / WIN - RAD;
        int dx = tid % WIN - RAD;
        float d2 = (float)(dx * dx + dy * dy);
        float invd = (d2 > 0.0f) ? rsqrtf(d2) : 1e30f;  // center: clamped later by 1e4 min
        s_lut[tid] = make_float2(invd, d2 * 0.125f);    // 1/(2*sigma^2)=0.125, sigma=2
    }

    // ---- cooperative halo load ----
    for (int i = tid; i < NPIX; i += TX * TY) {
        int hy = i / HALO_W;
        int hx = i - hy * HALO_W;
        int gx = x0 + hx - RAD;
        int gy = y0 + hy - RAD;
        float4 cz = make_float4(0.f, 0.f, 0.f, 0.f);
        float4 nn = make_float4(0.f, 0.f, 0.f, 0.f);   // zero normal => weight 0 (OOB mask)
        if (gx >= 0 && gx < IMG_W && gy >= 0 && gy < IMG_H) {
            int base = (b * IMG_H + gy) * IMG_W + gx;
            const float* cp = col + base * 3;
            cz.x = cp[0]; cz.y = cp[1]; cz.z = cp[2];
            const float* np = nrm + base * 3;
            nn.x = np[0]; nn.y = np[1]; nn.z = np[2];
            cz.w = zdz[base * 2];
        }
        s_colz[i] = cz;
        s_nrm[i]  = nn;
    }
    __syncthreads();

    // ---- per-pixel center data (2 vertically adjacent pixels per thread) ----
    const int r0 = ty * PPT;   // first pixel row within tile
    float cnx[PPT], cny[PPT], cnz[PPT], czv[PPT], rcpdz[PPT];
    float4 acc[PPT];
    #pragma unroll
    for (int p = 0; p < PPT; ++p) {
        int ci = (r0 + p + RAD) * HALO_W + tx + RAD;
        float4 n = s_nrm[ci];
        cnx[p] = n.x; cny[p] = n.y; cnz[p] = n.z;
        czv[p] = s_colz[ci].w;
        int gy = y0 + r0 + p;
        int gx = x0 + tx;
        float cdz = zdz[((b * IMG_H + gy) * IMG_W + gx) * 2 + 1];
        rcpdz[p] = 1.0f / cdz;                  // inf ok: min-clamped per tap
        acc[p] = make_float4(0.f, 0.f, 0.f, 0.f);
    }

    // ---- tap evaluation for pixel p at (dy,dx); lut already fetched ----
    auto tap = [&](const float4& t, const float4& n, float2 lut, int p) {
        float d = fmaf(cnx[p], n.x, fmaf(cny[p], n.y, cnz[p] * n.z));
        d = __saturatef(d);
        d = d * d; d = d * d; d = d * d; d = d * d;     // ^16
        d = d * d; d = d * d; d = d * d;                // ^128
        float adz = fabsf(t.w - czv[p]);
        float inv = fminf(rcpdz[p] * lut.x, 1e4f);      // 1/max(c_dz*dist, 1e-4)
        float arg = fmaf(adz, inv, lut.y);              // |dz|/denom + d^2/(2*var)
        float wt  = d * __expf(-arg);                   // w_n * w_xy * w_d
        acc[p].x = fmaf(t.x, wt, acc[p].x);
        acc[p].y = fmaf(t.y, wt, acc[p].y);
        acc[p].z = fmaf(t.z, wt, acc[p].z);
        acc[p].w += wt;
    };

    // ---- one halo row: each loaded tap serves up to PPT pixels ----
    auto row = [&](int ry, bool dop0, bool dop1) {
        int rowb = (r0 + ry + RAD) * HALO_W + tx;   // + dx index 0..10 below
        #pragma unroll
        for (int dxi = 0; dxi < WIN; ++dxi) {
            float4 t = s_colz[rowb + dxi];
            float4 n = s_nrm[rowb + dxi];
            if (dop0) { tap(t, n, s_lut[(ry + RAD) * WIN + dxi], 0); }
            if (dop1) { tap(t, n, s_lut[(ry - 1 + RAD) * WIN + dxi], 1); }
        }
    };

    row(-RAD, true, false);                       // ry=-5: only pixel 0
    for (int ry = -RAD + 1; ry <= RAD; ++ry)      // ry=-4..5: both pixels
        row(ry, true, true);
    row(RAD + 1, false, true);                    // ry=6: only pixel 1

    // ---- writeback ----
    #pragma unroll
    for (int p = 0; p < PPT; ++p) {
        int gy = y0 + r0 + p;
        int gx = x0 + tx;
        int o = ((b * IMG_H + gy) * IMG_W + gx) * 3;
        float iw = 1.0f / acc[p].w;   // center tap guarantees acc.w > 0
        out[o]     = acc[p].x * iw;
        out[o + 1] = acc[p].y * iw;
        out[o + 2] = acc[p].z * iw;
    }
}

extern "C" void kernel_launch(void* const* d_in, const int* in_sizes, int n_in,
                              void* d_out, int out_size)
{
    const float* col = (const float*)d_in[0];
    const float* nrm = (const float*)d_in[1];
    const float* zdz = (const float*)d_in[2];
    float* out = (float*)d_out;

    dim3 block(TX, TY);
    dim3 grid(IMG_W / TX, IMG_H / TILE_H, 4);
    bilateral_kernel<<<grid, block>>>(col, nrm, zdz, out);
}

// round 2
// speedup vs baseline: 1.7900x; 1.7900x over previous
#include <cuda_runtime.h>

#define RAD 5
#define WIN 11
#define TX 32
#define TY 8
#define PPT 2
#define TILE_H (TY * PPT)            // 16
#define HALO_W (TX + 2 * RAD)        // 42
#define HALO_H (TILE_H + 2 * RAD)    // 26
#define NPIX   (HALO_W * HALO_H)     // 1092
#define IMG_H 1024
#define IMG_W 1024

#define L2E 1.4426950408889634f

__device__ __forceinline__ float ex2f(float x) {
    float r; asm("ex2.approx.f32 %0, %1;" : "=f"(r) : "f"(x)); return r;
}
__device__ __forceinline__ float lg2f(float x) {
    float r; asm("lg2.approx.f32 %0, %1;" : "=f"(r) : "f"(x)); return r;
}

__global__ __launch_bounds__(TX * TY)
void bilateral_kernel(const float* __restrict__ col,
                      const float* __restrict__ nrm,
                      const float* __restrict__ zdz,
                      float* __restrict__ out)
{
    __shared__ float4 s_colz[NPIX];        // col.rgb, z
    __shared__ float4 s_nrm[NPIX];         // nrm.xyz, pad
    __shared__ float2 s_lut[WIN * WIN];    // (1/dist, dist^2/8 * log2e)

    const int tx = threadIdx.x;
    const int ty = threadIdx.y;
    const int tid = ty * TX + tx;
    const int b  = blockIdx.z;
    const int x0 = blockIdx.x * TX;
    const int y0 = blockIdx.y * TILE_H;

    // ---- fill LUT (121 entries) ----
    if (tid < WIN * WIN) {
        int dy = tid / WIN - RAD;
        int dx = tid % WIN - RAD;
        float d2 = (float)(dx * dx + dy * dy);
        float invd = (d2 > 0.0f) ? rsqrtf(d2) : 1e30f;   // center clamped by min below
        s_lut[tid] = make_float2(invd, d2 * 0.125f * L2E);
    }

    // ---- cooperative halo load ----
    for (int i = tid; i < NPIX; i += TX * TY) {
        int hy = i / HALO_W;
        int hx = i - hy * HALO_W;
        int gx = x0 + hx - RAD;
        int gy = y0 + hy - RAD;
        float4 cz = make_float4(0.f, 0.f, 0.f, 0.f);
        float4 nn = make_float4(0.f, 0.f, 0.f, 0.f);   // zero normal => lg2(0) = -inf => weight 0
        if (gx >= 0 && gx < IMG_W && gy >= 0 && gy < IMG_H) {
            int base = (b * IMG_H + gy) * IMG_W + gx;
            const float* cp = col + base * 3;
            cz.x = cp[0]; cz.y = cp[1]; cz.z = cp[2];
            const float* np = nrm + base * 3;
            nn.x = np[0]; nn.y = np[1]; nn.z = np[2];
            cz.w = zdz[base * 2];
        }
        s_colz[i] = cz;
        s_nrm[i]  = nn;
    }
    __syncthreads();

    // ---- per-pixel center data (2 vertically adjacent pixels per thread) ----
    const int r0 = ty * PPT;
    float cnx[PPT], cny[PPT], cnz[PPT], czv[PPT], rcpdz2[PPT];
    float4 acc[PPT];
    #pragma unroll
    for (int p = 0; p < PPT; ++p) {
        int ci = (r0 + p + RAD) * HALO_W + tx + RAD;
        float4 n = s_nrm[ci];
        cnx[p] = n.x; cny[p] = n.y; cnz[p] = n.z;
        czv[p] = s_colz[ci].w;
        int gy = y0 + r0 + p;
        int gx = x0 + tx;
        float cdz = zdz[((b * IMG_H + gy) * IMG_W + gx) * 2 + 1];
        rcpdz2[p] = L2E / cdz;                 // inf ok: min-clamped per tap
        acc[p] = make_float4(0.f, 0.f, 0.f, 0.f);
    }

    // ---- tap evaluation, fully in exp2 domain:
    //   w = exp2( 128*log2(max(dot,0)) - (|dz|*min(L2E/(c_dz*dist), 1e4*L2E) + d2/8*L2E) )
    auto tap = [&](const float4& t, const float4& n, float2 lut, int p) {
        float d   = fmaf(cnx[p], n.x, fmaf(cny[p], n.y, cnz[p] * n.z));
        float lg  = lg2f(fmaxf(d, 0.0f));               // -inf at 0 => w = 0
        float adz = fabsf(t.w - czv[p]);
        float inv = fminf(rcpdz2[p] * lut.x, 1e4f * L2E);
        float arg = fmaf(adz, inv, lut.y);
        float wt  = ex2f(fmaf(lg, 128.0f, -arg));
        acc[p].x = fmaf(t.x, wt, acc[p].x);
        acc[p].y = fmaf(t.y, wt, acc[p].y);
        acc[p].z = fmaf(t.z, wt, acc[p].z);
        acc[p].w += wt;
    };

    // ---- one halo row: each loaded tap serves up to PPT pixels ----
    auto row = [&](int ry, bool dop0, bool dop1) {
        int rowb = (r0 + ry + RAD) * HALO_W + tx;
        #pragma unroll
        for (int dxi = 0; dxi < WIN; ++dxi) {
            float4 t = s_colz[rowb + dxi];
            float4 n = s_nrm[rowb + dxi];
            if (dop0) { tap(t, n, s_lut[(ry + RAD) * WIN + dxi], 0); }
            if (dop1) { tap(t, n, s_lut[(ry - 1 + RAD) * WIN + dxi], 1); }
        }
    };

    row(-RAD, true, false);                       // ry=-5: only pixel 0
    for (int ry = -RAD + 1; ry <= RAD; ++ry)      // ry=-4..5: both pixels
        row(ry, true, true);
    row(RAD + 1, false, true);                    // ry=6: only pixel 1

    // ---- writeback ----
    #pragma unroll
    for (int p = 0; p < PPT; ++p) {
        int gy = y0 + r0 + p;
        int gx = x0 + tx;
        int o = ((b * IMG_H + gy) * IMG_W + gx) * 3;
        float iw = 1.0f / acc[p].w;   // center tap guarantees acc.w > 0
        out[o]     = acc[p].x * iw;
        out[o + 1] = acc[p].y * iw;
        out[o + 2] = acc[p].z * iw;
    }
}

extern "C" void kernel_launch(void* const* d_in, const int* in_sizes, int n_in,
                              void* d_out, int out_size)
{
    const float* col = (const float*)d_in[0];
    const float* nrm = (const float*)d_in[1];
    const float* zdz = (const float*)d_in[2];
    float* out = (float*)d_out;

    dim3 block(TX, TY);
    dim3 grid(IMG_W / TX, IMG_H / TILE_H, 4);
    bilateral_kernel<<<grid, block>>>(col, nrm, zdz, out);
}